// round 8
// baseline (speedup 1.0000x reference)
#include <cuda_runtime.h>

// Geometry: (1, D=24, H=24, W=16, C=2); N = 9216. i = z*384 + y*16 + x.
#define NV 9216
#define NB 96       // 48 moment blocks (c,z-slab) + 48 spatial blocks (c,y-plane)
#define NT 384
#define AA 1.953125e-5f   // a = 1/(2*160^2) = 1/51200

// Bilateral kernel = exp(-a||dp||^2) * intensity.
//   intensity: rank-5 Taylor  exp(-(Ii-Ij)^2/18) = gi gj sum_k ck Ii^k Ij^k   (err 1.4e-7)
//   spatial:   exp(-s) ~ 1 - s + s^2/2, s = a||dp||^2 <= 0.025               (err 2.6e-6)
// => bilateral blur of field v reduces to 15 global moments of v (deg<=4 in p).
// The theta=3 spatial CRF kernel stays exact/separable: z-blur in-phase, x/y
// contraction applied on demand by consumers.

__device__ float g_zq[2][2][NV];       // ping-pong z-blurred q fields per class
__device__ float g_mp[2][2][24][64];   // moment partials [pp][class][slab][5k*10j]
__device__ float g_np[24][64];         // norm-moment partials (rgb-only, iter 1)
__device__ int   g_flags[NB][32];      // per-block monotonic flags, 128B apart

__device__ __forceinline__ int ld_acq(const int* p) {
    int v; asm volatile("ld.global.acquire.gpu.b32 %0, [%1];" : "=r"(v) : "l"(p) : "memory");
    return v;
}
__device__ __forceinline__ void st_rel(int* p, int v) {
    asm volatile("st.global.release.gpu.b32 [%0], %1;" :: "l"(p), "r"(v) : "memory");
}
// Flat flag-array grid barrier (R6 design, 96 flags). Monotonic => replay-safe.
__device__ __forceinline__ void gridbar(int& target) {
    __syncthreads();
    target += 1;
    if (threadIdx.x == 0) st_rel(&g_flags[blockIdx.x][0], target);
    const int t = threadIdx.x; int v;
    do { v = (t < NB) ? ld_acq(&g_flags[t][0]) : target; }
    while (__syncthreads_count(v >= target) < NT);
}

// Evaluate (1 - s + s^2/2)-filter response at position (z,y,x) from 15 moments:
// M[0]=M0 M[1..3]=Mp M[4]=Mu M[5]=Muu M[6..8]=Mup M[9..14]=S(zz,yy,xx,zy,zx,yx)
__device__ __forceinline__ float EVAL(const float* M, float z, float y, float x,
                                      float R2, float R4) {
    float rM1  = z*M[1] + y*M[2] + x*M[3];
    float rMup = z*M[6] + y*M[7] + x*M[8];
    float rSr  = z*z*M[9] + y*y*M[10] + x*x*M[11]
               + 2.f*(z*y*M[12] + z*x*M[13] + y*x*M[14]);
    float t1 = R2*M[0] - 2.f*rM1 + M[4];
    float t2 = R4*M[0] + 2.f*R2*M[4] + M[5] - 4.f*(R2*rM1 + rMup) + 4.f*rSr;
    return M[0] - AA*t1 + (0.5f*AA*AA)*t2;
}

__global__ void __launch_bounds__(NT, 1)
crf_kernel(const float* __restrict__ u, const float* __restrict__ rgb,
           const float* __restrict__ ws, const float* __restrict__ wb,
           const float* __restrict__ Mc, float* __restrict__ out)
{
    __shared__ float ks24[576], ks16[256];     // theta=3 axis kernels
    __shared__ float fmom[15 * 16];            // finalized moments (15 fields x 15)
    __shared__ float sA[2 * 384];              // stage / ty buffers (both classes)
    __shared__ float sB[2 * 384];              // ty (moment) / qbuf (spatial)
    __shared__ float wpart[12 * 100];          // per-warp reduction partials

    const int b = blockIdx.x, t = threadIdx.x;
    int target = ld_acq(&g_flags[b][0]);       // replay-safe epoch base

    for (int idx = t; idx < 576; idx += NT) {
        float d = (float)(idx / 24) - (float)(idx % 24);
        ks24[idx] = __expf(-d * d * (1.f / 18.f));
    }
    for (int idx = t; idx < 256; idx += NT) {
        float d = (float)(idx / 16) - (float)(idx % 16);
        ks16[idx] = __expf(-d * d * (1.f / 18.f));
    }
    __syncthreads();

    const bool isMom = (b < 48);
    const int c = isMom ? (b & 1) : ((b - 48) & 1);
    const int zslab = b >> 1;                  // moment blocks
    const int yplane = (b - 48) >> 1;          // spatial blocks
    int iz, iy, ix;
    if (isMom) { iz = zslab;  iy = t >> 4; ix = t & 15; }
    else       { iz = t >> 4; iy = yplane; ix = t & 15; }
    const int i = iz * 384 + iy * 16 + ix;
    const float zf = (float)iz, yf = (float)iy, xf = (float)ix;
    const float R2 = zf*zf + yf*yf + xf*xf, R4 = R2 * R2;

    // Exact separable spatial normalizer (row-sum product), per voxel.
    float Szv = 0.f, Syv = 0.f, Sxv = 0.f;
    #pragma unroll
    for (int p = 0; p < 24; ++p) { Szv += ks24[p*24 + iz]; Syv += ks24[p*24 + iy]; }
    #pragma unroll
    for (int p = 0; p < 16; ++p) Sxv += ks16[p*16 + ix];
    const float inv_ns = 1.f / (Szv * Syv * Sxv);

    const float Iv = rgb[i];
    const float eI = __expf(-(1.f / 18.f) * Iv * Iv);
    const float ckc[5] = {1.f, 0.111111111f, 0.0061728395f,
                          2.28623686e-4f, 6.35066338e-6f};
    float ckIp[5], bfk[5];
    { float Ip = 1.f;
      #pragma unroll
      for (int k = 0; k < 5; ++k) { ckIp[k] = ckc[k] * Ip; bfk[k] = eI * Ip; Ip *= Iv; } }
    const float u_c = u[2 * i + c];
    const float ws0 = ws[0], ws1 = ws[1], wb0 = wb[0], wb1 = wb[1];
    const float M00 = Mc[0], M01 = Mc[1], M10 = Mc[2], M11 = Mc[3];
    const float wloc = yf*yf + xf*xf;          // slab-2D radial coordinate
    const int lane = t & 31, wid = t >> 5;

    for (int it = 1; it <= 6; ++it) {          // it=6 is the epilogue
        const int ppo = it & 1, ppi = ppo ^ 1;
        if (it == 6 && !isMom) break;          // spatial blocks done after bar 5

        float q;
        if (it == 1) {
            q = u_c;
        } else {
            // ---- staging / on-demand spatial y-contraction ----
            if (isMom) {
                sA[t]       = __ldcg(&g_zq[ppi][0][i]);
                sA[384 + t] = __ldcg(&g_zq[ppi][1][i]);
            } else {
                float a0 = 0.f, a1 = 0.f;
                const int base = (t >> 4) * 384 + (t & 15);
                #pragma unroll
                for (int yp = 0; yp < 24; ++yp) {
                    float kk = ks24[yp*24 + iy];
                    a0 += kk * __ldcg(&g_zq[ppi][0][base + yp*16]);
                    a1 += kk * __ldcg(&g_zq[ppi][1][base + yp*16]);
                }
                sA[t] = a0; sA[384 + t] = a1;  // ty(z,xp) both classes
            }
            // ---- finalize 15 fields x 15 moments from slab partials ----
            if (t < 225) {
                int f = t / 15, m = t % 15;
                const float* src = (f < 10) ? &g_mp[ppi][f & 1][0][(f >> 1) * 10]
                                            : &g_np[0][(f - 10) * 10];
                const int   J1[15] = {0,0,1,2,0,0,0,1,2,0,7,8,1,2,9};
                const int   E1[15] = {0,1,0,0,2,4,3,2,2,2,0,0,1,1,0};
                const int   J2[15] = {0,0,0,0,3,3,3,5,6,0,0,0,0,0,0};
                const int   E2[15] = {0,0,0,0,0,2,1,0,0,0,0,0,0,0,0};
                const float K2[15] = {0,0,0,0,1,2,1,1,1,0,0,0,0,0,0};
                int j1 = J1[m], e1 = E1[m], j2 = J2[m], e2 = E2[m];
                float k2 = K2[m], k3 = (m == 5) ? 1.f : 0.f;
                float acc = 0.f;
                #pragma unroll 8
                for (int z = 0; z < 24; ++z) {
                    float zz = (float)z, z2 = zz*zz, z3 = z2*zz, z4 = z2*z2;
                    float p1 = (e1 == 0) ? 1.f : (e1 == 1) ? zz : (e1 == 2) ? z2
                             : (e1 == 3) ? z3 : z4;
                    float p2 = (e2 == 0) ? 1.f : (e2 == 1) ? zz : z2;
                    const float* r = src + z * 64;
                    acc += p1 * __ldcg(r + j1) + k2 * p2 * __ldcg(r + j2)
                         + k3 * __ldcg(r + 4);
                }
                fmom[f * 16 + m] = acc;
            }
            __syncthreads();
            // ---- complete exact spatial filter (x / xy contraction) ----
            float sp0, sp1;
            if (isMom) {
                float t0 = 0.f, t1v = 0.f;
                #pragma unroll
                for (int yp = 0; yp < 24; ++yp) {
                    float kk = ks24[yp*24 + iy];
                    t0  += kk * sA[yp*16 + ix];
                    t1v += kk * sA[384 + yp*16 + ix];
                }
                sB[t] = t0; sB[384 + t] = t1v;
                __syncthreads();
                float s0 = 0.f, s1 = 0.f;
                #pragma unroll
                for (int xp = 0; xp < 16; ++xp) {
                    float kk = ks16[xp*16 + ix];
                    s0 += kk * sB[iy*16 + xp];
                    s1 += kk * sB[384 + iy*16 + xp];
                }
                sp0 = s0; sp1 = s1;
            } else {
                float s0 = 0.f, s1 = 0.f;
                #pragma unroll
                for (int xp = 0; xp < 16; ++xp) {
                    float kk = ks16[xp*16 + ix];
                    s0 += kk * sA[iz*16 + xp];
                    s1 += kk * sA[384 + iz*16 + xp];
                }
                sp0 = s0; sp1 = s1;
            }
            // ---- messages + q update ----
            float num0 = 0.f, num1 = 0.f, nbv = 0.f;
            #pragma unroll
            for (int k = 0; k < 5; ++k) {
                float cw = ckIp[k];
                num0 += cw * EVAL(&fmom[(2*k + 0) * 16], zf, yf, xf, R2, R4);
                num1 += cw * EVAL(&fmom[(2*k + 1) * 16], zf, yf, xf, R2, R4);
                nbv  += cw * EVAL(&fmom[(10 + k) * 16], zf, yf, xf, R2, R4);
            }
            float inb = 1.f / nbv;
            float m0 = sp0 * inv_ns * ws0 + num0 * inb * wb0;
            float m1 = sp1 * inv_ns * ws1 + num1 * inb * wb1;
            float pw = (c == 0) ? (m0 * M00 + m1 * M01) : (m0 * M10 + m1 * M11);
            q = u_c - pw;
        }

        if (it == 6) {                          // epilogue: write final q
            out[2 * i + c] = q;
            break;
        }

        if (isMom) {
            // ---- accumulate 5 fields x 10 slab-2D moments of v_k = eI*I^k*q ----
            float pj[10] = {1.f, yf, xf, wloc, wloc*wloc, wloc*yf, wloc*xf,
                            yf*yf, xf*xf, yf*xf};
            #pragma unroll
            for (int k = 0; k < 5; ++k) {
                float v = bfk[k] * q;
                #pragma unroll
                for (int j = 0; j < 10; ++j) {
                    float r = v * pj[j];
                    #pragma unroll
                    for (int o = 16; o > 0; o >>= 1)
                        r += __shfl_xor_sync(0xffffffffu, r, o);
                    if (lane == 0) wpart[wid * 100 + k * 10 + j] = r;
                }
            }
            const bool donorm = (it == 1) && (c == 0);   // rgb-only norm moments
            if (donorm) {
                #pragma unroll
                for (int k = 0; k < 5; ++k) {
                    float v = bfk[k];
                    #pragma unroll
                    for (int j = 0; j < 10; ++j) {
                        float r = v * pj[j];
                        #pragma unroll
                        for (int o = 16; o > 0; o >>= 1)
                            r += __shfl_xor_sync(0xffffffffu, r, o);
                        if (lane == 0) wpart[wid * 100 + 50 + k * 10 + j] = r;
                    }
                }
            }
            __syncthreads();
            if (t < 50) {
                float a = 0.f;
                #pragma unroll
                for (int w = 0; w < 12; ++w) a += wpart[w * 100 + t];
                g_mp[ppo][c][zslab][t] = a;
            }
            if (donorm && t >= 50 && t < 100) {
                float a = 0.f;
                #pragma unroll
                for (int w = 0; w < 12; ++w) a += wpart[w * 100 + t];
                g_np[zslab][t - 50] = a;
            }
        } else {
            // ---- exact theta=3 z-blur within this y-plane ----
            sB[t] = q;
            __syncthreads();
            float acc = 0.f;
            #pragma unroll
            for (int zp = 0; zp < 24; ++zp)
                acc += ks24[zp*24 + iz] * sB[zp*16 + ix];
            g_zq[ppo][c][i] = acc;
        }
        gridbar(target);
    }
}

// ---------------------------------------------------------------------------
// Inputs (metadata order): unaries[18432] f32, rgb[9216] f32,
// spatial_ker_weights[2] f32, bilateral_ker_weights[2] f32,
// compatibility_matrix[4] f32 (row-major). Output: float32 [18432].
// ---------------------------------------------------------------------------
extern "C" void kernel_launch(void* const* d_in, const int* in_sizes, int n_in,
                              void* d_out, int out_size) {
    const float* u   = (const float*)d_in[0];
    const float* rgb = (const float*)d_in[1];
    const float* ws  = (const float*)d_in[2];
    const float* wb  = (const float*)d_in[3];
    const float* Mc  = (const float*)d_in[4];
    crf_kernel<<<NB, NT>>>(u, rgb, ws, wb, Mc, (float*)d_out);
}

// round 9
// speedup vs baseline: 2.6985x; 2.6985x over previous
#include <cuda_runtime.h>

// Geometry: (1, D=24, H=24, W=16, C=2); N = 9216 voxels.
#define NV   9216
#define NB   144     // blocks; <= 148 SMs so all co-resident (safe grid barrier)
#define NT   384

// Taylor rank-5 factorization of the bilateral intensity kernel:
//   exp(-(Ii-Ij)^2/18) = e^{-Ii^2/18} e^{-Ij^2/18} * sum_k c_k Ii^k Ij^k,
//   c_k = (1/9)^k / k!,  truncation error ~1.4e-7.
// Basis fields f = 2k+c (k=0..4, c=0..1); spatial fields f = 10+c.
// Block b owns fields f0=b/24, f1=f0+6 and slab/plane zy=b%24.
// Group g = f0 (24 blocks): phase1->phase2 dependency is group-local.

__device__ float g_xy[18][NV];      // xy-blurred fields (12..17 = norm, iter 1)
__device__ float g_zb[2][12][NV];   // ping-pong z-blurred basis fields
__device__ float g_nrm[6][NV];      // z-blurred norm fields (write-once, iter 1)
__device__ int   g_flags[NB][32];   // global-barrier flags, monotonic, 128B apart
__device__ int   g_gflags[NB][32];  // group-barrier flags, monotonic

__device__ __forceinline__ int ld_acq(const int* p) {
    int v; asm volatile("ld.global.acquire.gpu.b32 %0, [%1];" : "=r"(v) : "l"(p) : "memory");
    return v;
}
__device__ __forceinline__ void st_rel(int* p, int v) {
    asm volatile("st.global.release.gpu.b32 [%0], %1;" :: "l"(p), "r"(v) : "memory");
}

// Global barrier: parallel arrivals on 144 distinct lines; 5 warps poll
// autonomously (no block-wide sync per round). Monotonic => replay-safe.
__device__ __forceinline__ void bar_global(int& tg) {
    __syncthreads();                       // data writes done, block-wide
    tg += 1;
    const int t = threadIdx.x;
    if (t == 0) st_rel(&g_flags[blockIdx.x][0], tg);
    if (t < 160) {
        bool ok;
        do {
            ok = (t < NB) ? (ld_acq(&g_flags[t][0]) >= tg) : true;
        } while (!__all_sync(0xffffffffu, ok));
    }
    __syncthreads();
}

// Group barrier (24 blocks sharing field pair): one warp polls 24 flags.
__device__ __forceinline__ void bar_group(int& tgp, int gb) {
    __syncthreads();
    tgp += 1;
    const int t = threadIdx.x;
    if (t == 0) st_rel(&g_gflags[blockIdx.x][0], tgp);
    if (t < 32) {
        bool ok;
        do {
            ok = (t < 24) ? (ld_acq(&g_gflags[gb + t][0]) >= tgp) : true;
        } while (!__all_sync(0xffffffffu, ok));
    }
    __syncthreads();
}

// Message reconstruction at voxel i from z-blurred fields (ping-pong side sp).
// e^{-aI^2} prefactor cancels between numerator and normalizer.
__device__ __forceinline__ void compute_msgs(
    int i, int sp, float Iv, float ws0, float ws1, float wb0, float wb1,
    float& m0, float& m1)
{
    const float ck[5] = {1.0f, 0.111111111f, 0.0061728395f,
                         2.28623686e-4f, 6.35066338e-6f};
    float p = 1.0f, nb = 0.f, b0 = 0.f, b1 = 0.f;
    #pragma unroll
    for (int k = 0; k < 5; ++k) {
        float cp = ck[k] * p;
        nb += cp * __ldcg(&g_nrm[k][i]);
        b0 += cp * __ldcg(&g_zb[sp][2 * k + 0][i]);
        b1 += cp * __ldcg(&g_zb[sp][2 * k + 1][i]);
        p *= Iv;
    }
    float inb = 1.0f / nb;
    float ins = 1.0f / __ldcg(&g_nrm[5][i]);
    m0 = __ldcg(&g_zb[sp][10][i]) * ins * ws0 + b0 * inb * wb0;
    m1 = __ldcg(&g_zb[sp][11][i]) * ins * ws1 + b1 * inb * wb1;
}

// ---------------------------------------------------------------------------
// Per iteration: phase1 (q rebuild + x/y blur, slab zy) -> GROUP barrier ->
// phase2 (z blur, plane zy, same field pair => group-local dep) -> GLOBAL
// barrier. 5 group + 5 global barriers total.
// ---------------------------------------------------------------------------
__global__ void __launch_bounds__(NT, 1)
crf_kernel(const float* __restrict__ u, const float* __restrict__ rgb,
           const float* __restrict__ ws, const float* __restrict__ wb,
           const float* __restrict__ Mc, float* __restrict__ out)
{
    __shared__ float kb24[576], ks24[576];   // bilateral (theta=160) / spatial (theta=3)
    __shared__ float kb16[256], ks16[256];
    __shared__ float Sin[3 * 384], Smid[3 * 384];

    const int b = blockIdx.x, t = threadIdx.x;
    // Replay-safe epoch bases: this block's own flags (its last written values).
    int tg  = ld_acq(&g_flags[b][0]);
    int tgp = ld_acq(&g_gflags[b][0]);

    for (int idx = t; idx < 576; idx += NT) {
        float d = (float)(idx / 24) - (float)(idx % 24), d2 = d * d;
        kb24[idx] = __expf(-d2 * (0.5f / 25600.f));
        ks24[idx] = __expf(-d2 * (0.5f / 9.f));
    }
    for (int idx = t; idx < 256; idx += NT) {
        float d = (float)(idx / 16) - (float)(idx % 16), d2 = d * d;
        kb16[idx] = __expf(-d2 * (0.5f / 25600.f));
        ks16[idx] = __expf(-d2 * (0.5f / 9.f));
    }
    // (first __syncthreads in phase1 orders kmat writes before reads)

    const float ws0 = ws[0], ws1 = ws[1], wb0 = wb[0], wb1 = wb[1];
    const float M00 = Mc[0], M01 = Mc[1], M10 = Mc[2], M11 = Mc[3];
    const float A = 1.0f / 18.0f;

    const int f0 = b / 24, zy = b % 24;      // slab (phase1) == plane (phase2)
    const int f1 = f0 + 6;
    const int gb = f0 * 24;                  // group base block id
    const int c  = f0 & 1;                   // both fields share the class
    const bool bil1 = (f1 < 10);
    const int i  = zy * 384 + t;             // phase1 voxel
    const int yy = t >> 4, xx = t & 15;      // in-slab coords (yy is z in phase2)

    const float* k16u1 = bil1 ? kb16 : ks16;
    const float* k24u1 = bil1 ? kb24 : ks24;
    const float* k16un = (f0 < 5) ? kb16 : ks16;
    const float* k24un = (f0 < 5) ? kb24 : ks24;

    // Per-thread constants (fixed across iterations)
    const float Iv = rgb[i];
    const float eI = __expf(-A * Iv * Iv);
    float Ip[5]; Ip[0] = 1.f;
    #pragma unroll
    for (int k = 1; k < 5; ++k) Ip[k] = Ip[k - 1] * Iv;
    const float bf0 = eI * Ip[f0 >> 1];                    // unit0: always bilateral
    const float bf1 = bil1 ? eI * Ip[f1 >> 1] : 1.f;       // unit1
    const float bfn = (f0 < 5) ? eI * Ip[f0] : 1.f;        // norm unit (iter 1)
    const float u_c = u[2 * i + c];

    const int poff = (t >> 4) * 384 + zy * 16 + (t & 15);  // phase2 plane-load idx
    const int oi   = yy * 384 + zy * 16 + xx;              // phase2 output voxel

    for (int it = 1; it <= 5; ++it) {
        const int pp = it & 1, sp = pp ^ 1;  // write side / read side of g_zb
        // ------------- phase 1: q rebuild + x/y blur -------------
        float q;
        if (it == 1) {
            q = u_c;
        } else {
            float m0, m1;
            compute_msgs(i, sp, Iv, ws0, ws1, wb0, wb1, m0, m1);
            float pw = (c == 0) ? (m0 * M00 + m1 * M01) : (m0 * M10 + m1 * M11);
            q = u_c - pw;
        }
        Sin[0 * 384 + t] = bf0 * q;
        Sin[1 * 384 + t] = bf1 * q;
        if (it == 1) Sin[2 * 384 + t] = bfn;
        __syncthreads();
        {   // x-pass
            float a0 = 0.f, a1 = 0.f, a2 = 0.f;
            #pragma unroll
            for (int xp = 0; xp < 16; ++xp) {
                float s0 = Sin[0 * 384 + (yy << 4) + xp];
                float s1 = Sin[1 * 384 + (yy << 4) + xp];
                a0 += kb16 [xp * 16 + xx] * s0;
                a1 += k16u1[xp * 16 + xx] * s1;
            }
            if (it == 1) {
                #pragma unroll
                for (int xp = 0; xp < 16; ++xp)
                    a2 += k16un[xp * 16 + xx] * Sin[2 * 384 + (yy << 4) + xp];
            }
            Smid[0 * 384 + t] = a0;
            Smid[1 * 384 + t] = a1;
            if (it == 1) Smid[2 * 384 + t] = a2;
        }
        __syncthreads();
        {   // y-pass + global store
            float o0 = 0.f, o1 = 0.f, o2 = 0.f;
            #pragma unroll
            for (int yp = 0; yp < 24; ++yp) {
                float s0 = Smid[0 * 384 + (yp << 4) + xx];
                float s1 = Smid[1 * 384 + (yp << 4) + xx];
                o0 += kb24 [yp * 24 + yy] * s0;
                o1 += k24u1[yp * 24 + yy] * s1;
            }
            if (it == 1) {
                #pragma unroll
                for (int yp = 0; yp < 24; ++yp)
                    o2 += k24un[yp * 24 + yy] * Smid[2 * 384 + (yp << 4) + xx];
            }
            g_xy[f0][i] = o0;
            g_xy[f1][i] = o1;
            if (it == 1) g_xy[12 + f0][i] = o2;
        }
        bar_group(tgp, gb);      // phase2 reads only this group's g_xy fields

        // ------------- phase 2: z blur (plane y = zy) -------------
        Sin[0 * 384 + t] = __ldcg(&g_xy[f0][poff]);
        Sin[1 * 384 + t] = __ldcg(&g_xy[f1][poff]);
        if (it == 1) Sin[2 * 384 + t] = __ldcg(&g_xy[12 + f0][poff]);
        __syncthreads();
        {
            float o0 = 0.f, o1 = 0.f, o2 = 0.f;
            #pragma unroll
            for (int zp = 0; zp < 24; ++zp) {
                float s0 = Sin[0 * 384 + (zp << 4) + xx];
                float s1 = Sin[1 * 384 + (zp << 4) + xx];
                o0 += kb24 [zp * 24 + yy] * s0;   // yy == output z
                o1 += k24u1[zp * 24 + yy] * s1;
            }
            if (it == 1) {
                #pragma unroll
                for (int zp = 0; zp < 24; ++zp)
                    o2 += k24un[zp * 24 + yy] * Sin[2 * 384 + (zp << 4) + xx];
            }
            g_zb[pp][f0][oi] = o0;
            g_zb[pp][f1][oi] = o1;
            if (it == 1) g_nrm[f0][oi] = o2;
        }
        bar_global(tg);          // all fields visible for next compute_msgs
    }

    // ------------- final combine: q5 = u - message @ compat^T -------------
    // Iter-5 fields live in g_zb[1] (pp of it=5).
    if (t < 64) {
        int ii = b * 64 + t;
        float m0, m1;
        compute_msgs(ii, 1, rgb[ii], ws0, ws1, wb0, wb1, m0, m1);
        float2 o;
        o.x = u[2 * ii + 0] - (m0 * M00 + m1 * M01);
        o.y = u[2 * ii + 1] - (m0 * M10 + m1 * M11);
        reinterpret_cast<float2*>(out)[ii] = o;
    }
}

// ---------------------------------------------------------------------------
// Inputs (metadata order): unaries[18432] f32, rgb[9216] f32,
// spatial_ker_weights[2] f32, bilateral_ker_weights[2] f32,
// compatibility_matrix[4] f32 (row-major). Output: float32 [18432].
// ---------------------------------------------------------------------------
extern "C" void kernel_launch(void* const* d_in, const int* in_sizes, int n_in,
                              void* d_out, int out_size) {
    const float* u   = (const float*)d_in[0];
    const float* rgb = (const float*)d_in[1];
    const float* ws  = (const float*)d_in[2];
    const float* wb  = (const float*)d_in[3];
    const float* Mc  = (const float*)d_in[4];
    crf_kernel<<<NB, NT>>>(u, rgb, ws, wb, Mc, (float*)d_out);
}

// round 10
// speedup vs baseline: 3.2228x; 1.1943x over previous
#include <cuda_runtime.h>

// Geometry: (1, D=24, H=24, W=16, C=2); N = 9216 voxels. i = z*384 + y*16 + x.
#define NV   9216
#define NB   144     // <= 148 SMs: all co-resident (safe persistent barriers)
#define NT   384

// Taylor rank-5 factorization of the bilateral intensity kernel:
//   exp(-(Ii-Ij)^2/18) = e^{-Ii^2/18} e^{-Ij^2/18} * sum_k c_k Ii^k Ij^k  (err ~1.4e-7)
// Basis fields f = 2k+c (k=0..4, c=0..1); spatial fields f = 10+c.
// Block b: f0 = b/24, f1 = f0+6, slab z = b%24. Phase 2 re-role: output slab
// z = b%24, chunk c2 = b/24 (64 voxels). The 6 blocks {c*24+z} form the
// z-local producer/consumer set for q at slab z.

__device__ float  g_xy [2][12][NV];  // ping-pong xy-blurred basis fields
__device__ float  g_xyn[5][NV];      // xy-blurred norm basis (round 1 only)
__device__ float2 g_q[NV];           // q field (both classes), rebuilt each round
__device__ int    g_flags [NB][32];  // global-barrier flags, monotonic, 128B apart
__device__ int    g_lflags[NB][32];  // local-barrier flags, monotonic

__device__ __forceinline__ int ld_acq(const int* p) {
    int v; asm volatile("ld.global.acquire.gpu.b32 %0, [%1];" : "=r"(v) : "l"(p) : "memory");
    return v;
}
__device__ __forceinline__ void st_rel(int* p, int v) {
    asm volatile("st.global.release.gpu.b32 [%0], %1;" :: "l"(p), "r"(v) : "memory");
}

// Global barrier: 144 parallel arrivals; 5 warps poll autonomously.
__device__ __forceinline__ void bar_global(int& tg) {
    __syncthreads();
    tg += 1;
    const int t = threadIdx.x;
    if (t == 0) st_rel(&g_flags[blockIdx.x][0], tg);
    if (t < 160) {
        bool ok;
        do { ok = (t < NB) ? (ld_acq(&g_flags[t][0]) >= tg) : true; }
        while (!__all_sync(0xffffffffu, ok));
    }
    __syncthreads();
}

// Local barrier over the 6 blocks {c*24 + z}: one warp polls 6 flags.
__device__ __forceinline__ void bar_local(int& tl, int z) {
    __syncthreads();
    tl += 1;
    const int t = threadIdx.x;
    if (t == 0) st_rel(&g_lflags[blockIdx.x][0], tl);
    if (t < 32) {
        bool ok;
        do { ok = (t < 6) ? (ld_acq(&g_lflags[t * 24 + z][0]) >= tl) : true; }
        while (!__all_sync(0xffffffffu, ok));
    }
    __syncthreads();
}

// ---------------------------------------------------------------------------
// Per round r: phase1 (load q, xy-blur 2 fields, slab z) -> GLOBAL barrier ->
// phase2 (z-contract ALL 12 fields over 64-voxel chunk, build messages,
// write q -- or out at r=5) -> LOCAL(6) barrier. 5 global + 4 local syncs.
// ---------------------------------------------------------------------------
__global__ void __launch_bounds__(NT, 1)
crf_kernel(const float* __restrict__ u, const float* __restrict__ rgb,
           const float* __restrict__ ws, const float* __restrict__ wb,
           const float* __restrict__ Mc, float* __restrict__ out)
{
    __shared__ float kb24[576], ks24[576];   // bilateral (theta=160) / spatial (theta=3)
    __shared__ float kb16[256], ks16[256];
    __shared__ float S0[384], S1[384], S2[384];   // phase1 Sin / phase2 partials
    __shared__ float T0[384], T1[384], T2[384];   // phase1 Smid / phase2 norm partials

    const int b = blockIdx.x, t = threadIdx.x;
    int tg = ld_acq(&g_flags[b][0]);    // replay-safe epoch bases
    int tl = ld_acq(&g_lflags[b][0]);

    for (int idx = t; idx < 576; idx += NT) {
        float d = (float)(idx / 24) - (float)(idx % 24), d2 = d * d;
        kb24[idx] = __expf(-d2 * (0.5f / 25600.f));
        ks24[idx] = __expf(-d2 * (0.5f / 9.f));
    }
    for (int idx = t; idx < 256; idx += NT) {
        float d = (float)(idx / 16) - (float)(idx % 16), d2 = d * d;
        kb16[idx] = __expf(-d2 * (0.5f / 25600.f));
        ks16[idx] = __expf(-d2 * (0.5f / 9.f));
    }
    __syncthreads();

    const float ws0 = ws[0], ws1 = ws[1], wb0 = wb[0], wb1 = wb[1];
    const float M00 = Mc[0], M01 = Mc[1], M10 = Mc[2], M11 = Mc[3];

    const int f0 = b / 24, z = b % 24, c2 = f0;
    const int f1 = f0 + 6;
    const int c  = f0 & 1;
    const bool bil1 = (f1 < 10);
    const float* k16u1 = bil1 ? kb16 : ks16;
    const float* k24u1 = bil1 ? kb24 : ks24;

    // ---- phase1 per-thread constants (voxel i1 = full slab z) ----
    const int i1 = z * 384 + t;
    const int yy = t >> 4, xx = t & 15;
    const float Iv = rgb[i1];
    const float eI = __expf(-(1.f / 18.f) * Iv * Iv);
    float Ip[5]; Ip[0] = 1.f;
    #pragma unroll
    for (int k = 1; k < 5; ++k) Ip[k] = Ip[k - 1] * Iv;
    const float bf0 = eI * Ip[f0 >> 1];
    const float bf1 = bil1 ? eI * Ip[f1 >> 1] : 1.f;
    const float bfn = (f0 < 5) ? eI * Ip[f0] : 0.f;   // norm basis input (r1)
    const float u_c = u[2 * i1 + c];

    // ---- phase2 thread roles ----
    const int v = t & 63, j = t >> 6;        // j in 0..5: field pair
    const int cv = c2 * 64 + v;              // slab-local load index
    const int fA = (j < 5) ? 2 * j : 10;     // fields fA, fA+1
    const float* kk24 = (j < 5) ? kb24 : ks24;

    // ---- phase2 finalizer constants (t < 64; voxel i2, fixed all rounds) ----
    float ckIp2[5], inv_ns2 = 0.f, inv_nb = 0.f, u20 = 0.f, u21 = 0.f;
    const int i2 = z * 384 + c2 * 64 + t;    // valid for t<64
    if (t < 64) {
        float I2 = rgb[i2];
        const float ck[5] = {1.f, 0.111111111f, 0.0061728395f,
                             2.28623686e-4f, 6.35066338e-6f};
        float p = 1.f;
        #pragma unroll
        for (int k = 0; k < 5; ++k) { ckIp2[k] = ck[k] * p; p *= I2; }
        float2 uu = reinterpret_cast<const float2*>(u)[i2];
        u20 = uu.x; u21 = uu.y;
        int y2 = (c2 * 64 + t) >> 4, x2 = (c2 * 64 + t) & 15;
        float Sz = 0.f, Sy = 0.f, Sx = 0.f;   // exact separable spatial norm
        #pragma unroll
        for (int p24 = 0; p24 < 24; ++p24) {
            Sz += ks24[p24 * 24 + z]; Sy += ks24[p24 * 24 + y2];
        }
        #pragma unroll
        for (int p16 = 0; p16 < 16; ++p16) Sx += ks16[p16 * 16 + x2];
        inv_ns2 = 1.f / (Sz * Sy * Sx);
    }

    for (int r = 1; r <= 5; ++r) {
        const int side = r & 1;
        // ------------- phase 1: load q + x/y blur (slab z) -------------
        float q;
        if (r == 1) {
            q = u_c;
        } else {
            float2 qv = __ldcg(&g_q[i1]);
            q = (c == 0) ? qv.x : qv.y;
        }
        S0[t] = bf0 * q;
        S1[t] = bf1 * q;
        if (r == 1) S2[t] = bfn;
        __syncthreads();
        {   // x-pass
            float a0 = 0.f, a1 = 0.f, a2 = 0.f;
            #pragma unroll
            for (int xp = 0; xp < 16; ++xp) {
                a0 += kb16 [xp * 16 + xx] * S0[(yy << 4) + xp];
                a1 += k16u1[xp * 16 + xx] * S1[(yy << 4) + xp];
            }
            if (r == 1 && f0 < 5) {
                #pragma unroll
                for (int xp = 0; xp < 16; ++xp)
                    a2 += kb16[xp * 16 + xx] * S2[(yy << 4) + xp];
            }
            T0[t] = a0; T1[t] = a1;
            if (r == 1) T2[t] = a2;
        }
        __syncthreads();
        {   // y-pass + store
            float o0 = 0.f, o1 = 0.f, o2 = 0.f;
            #pragma unroll
            for (int yp = 0; yp < 24; ++yp) {
                o0 += kb24 [yp * 24 + yy] * T0[(yp << 4) + xx];
                o1 += k24u1[yp * 24 + yy] * T1[(yp << 4) + xx];
            }
            g_xy[side][f0][i1] = o0;
            g_xy[side][f1][i1] = o1;
            if (r == 1 && f0 < 5) {
                #pragma unroll
                for (int yp = 0; yp < 24; ++yp)
                    o2 += kb24[yp * 24 + yy] * T2[(yp << 4) + xx];
                g_xyn[f0][i1] = o2;
            }
        }
        bar_global(tg);

        // ------------- phase 2: z-contract all fields, build q -------------
        {
            float b0 = 0.f, b1 = 0.f;
            #pragma unroll
            for (int zp = 0; zp < 24; ++zp) {
                float w = kk24[zp * 24 + z];
                int idx = zp * 384 + cv;
                b0 += w * __ldcg(&g_xy[side][fA][idx]);
                b1 += w * __ldcg(&g_xy[side][fA + 1][idx]);
            }
            S0[(j << 6) + v] = b0;
            S1[(j << 6) + v] = b1;
            if (r == 1 && j < 5) {
                float bn = 0.f;
                #pragma unroll
                for (int zp = 0; zp < 24; ++zp)
                    bn += kb24[zp * 24 + z] * __ldcg(&g_xyn[j][zp * 384 + cv]);
                T0[(j << 6) + v] = bn;
            }
        }
        __syncthreads();
        if (t < 64) {
            float bb0 = 0.f, bb1 = 0.f;
            #pragma unroll
            for (int k = 0; k < 5; ++k) {
                bb0 += ckIp2[k] * S0[(k << 6) + t];
                bb1 += ckIp2[k] * S1[(k << 6) + t];
            }
            if (r == 1) {
                float nb = 0.f;
                #pragma unroll
                for (int k = 0; k < 5; ++k) nb += ckIp2[k] * T0[(k << 6) + t];
                inv_nb = 1.f / nb;
            }
            float m0 = S0[(5 << 6) + t] * inv_ns2 * ws0 + bb0 * inv_nb * wb0;
            float m1 = S1[(5 << 6) + t] * inv_ns2 * ws1 + bb1 * inv_nb * wb1;
            float2 qv;
            qv.x = u20 - (m0 * M00 + m1 * M01);
            qv.y = u21 - (m0 * M10 + m1 * M11);
            if (r == 5) reinterpret_cast<float2*>(out)[i2] = qv;
            else        g_q[i2] = qv;
        }
        if (r < 5) bar_local(tl, z);   // q producers == q consumers: 6 blocks
    }
}

// ---------------------------------------------------------------------------
// Inputs (metadata order): unaries[18432] f32, rgb[9216] f32,
// spatial_ker_weights[2] f32, bilateral_ker_weights[2] f32,
// compatibility_matrix[4] f32 (row-major). Output: float32 [18432].
// ---------------------------------------------------------------------------
extern "C" void kernel_launch(void* const* d_in, const int* in_sizes, int n_in,
                              void* d_out, int out_size) {
    const float* u   = (const float*)d_in[0];
    const float* rgb = (const float*)d_in[1];
    const float* ws  = (const float*)d_in[2];
    const float* wb  = (const float*)d_in[3];
    const float* Mc  = (const float*)d_in[4];
    crf_kernel<<<NB, NT>>>(u, rgb, ws, wb, Mc, (float*)d_out);
}